// round 9
// baseline (speedup 1.0000x reference)
#include <cuda_runtime.h>
#include <cstdint>

// ProbabilityAdjustedLoss: B=8388608 rows, logits[B,2] fp32, labels[B] int32.
// Fused single-kernel, BRANCHLESS row loss (labels are random -> the old
// label branch diverged every warp, doubling MUFU work + BSSY/BSYNC).
// One exp + one rcp gives both softmax probs; FSEL picks p/w; one log.

#define B_TOTAL 8388608
#define NPAIRS  (B_TOTAL / 2)          // 2 rows per iteration (float4 + int2)
#define GRID1   2048
#define BLK1    256

__device__ float        g_partials[GRID1];
__device__ unsigned int g_counter = 0;

__device__ __forceinline__ float row_loss(float l0, float l1, int lab) {
    float d   = l1 - l0;
    float e   = __expf(d);                       // e^(l1-l0)
    float p0  = __fdividef(1.0f, 1.0f + e);      // softmax prob of class 0
    float p1  = e * p0;                          // softmax prob of class 1
    // weights (both cheap FMA/FMNMX; stop_gradient irrelevant for fwd)
    float w0  = fmaxf(0.1f, 1.0f - fmaxf(0.0f, p0 - 0.95f) * 10.0f);
    float w1  = fmaxf(0.5f, 2.0f - fmaxf(0.0f, p1 - 0.05f) * (1.0f / 0.95f));
    bool stable = (lab == 0);
    float p = stable ? p0 : p1;                  // FSEL, no branch
    float w = stable ? w0 : w1;
    return -w * __logf(p + 1e-8f);
}

__global__ void __launch_bounds__(BLK1)
loss_fused(const float4* __restrict__ logits2,   // [NPAIRS] : 2 rows per float4
           const int2*   __restrict__ labels2,   // [NPAIRS] : 2 int32 labels per vec
           float* __restrict__ out) {
    float acc = 0.0f;
    const int stride = GRID1 * BLK1;             // 524288; NPAIRS/stride == 8 exactly
    int i = blockIdx.x * BLK1 + threadIdx.x;
    #pragma unroll 2
    for (int it = 0; it < NPAIRS / stride; it++, i += stride) {
        float4 lg = logits2[i];
        int2   lb = labels2[i];
        acc += row_loss(lg.x, lg.y, lb.x);
        acc += row_loss(lg.z, lg.w, lb.y);
    }

    // intra-block reduce (fp32 partial; fp64 happens on partials below)
    #pragma unroll
    for (int off = 16; off > 0; off >>= 1)
        acc += __shfl_xor_sync(0xFFFFFFFFu, acc, off);

    __shared__ float warp_sums[BLK1 / 32];
    int lane = threadIdx.x & 31;
    int wid  = threadIdx.x >> 5;
    if (lane == 0) warp_sums[wid] = acc;
    __syncthreads();

    __shared__ bool is_last;
    if (wid == 0) {
        float v = (lane < BLK1 / 32) ? warp_sums[lane] : 0.0f;
        #pragma unroll
        for (int off = 16; off > 0; off >>= 1)
            v += __shfl_xor_sync(0xFFFFFFFFu, v, off);
        if (lane == 0) {
            g_partials[blockIdx.x] = v;
            __threadfence();                      // partial visible before count
            unsigned int done = atomicAdd(&g_counter, 1u);
            is_last = (done == GRID1 - 1);
        }
    }
    __syncthreads();

    if (!is_last) return;

    // Final block: deterministic fixed-order fp64 reduction of all partials.
    double dacc = 0.0;
    for (int j = threadIdx.x; j < GRID1; j += BLK1)
        dacc += (double)g_partials[j];

    #pragma unroll
    for (int off = 16; off > 0; off >>= 1)
        dacc += __shfl_xor_sync(0xFFFFFFFFu, dacc, off);

    __shared__ double dwarp[BLK1 / 32];
    if (lane == 0) dwarp[wid] = dacc;
    __syncthreads();

    if (wid == 0) {
        double v = (lane < BLK1 / 32) ? dwarp[lane] : 0.0;
        #pragma unroll
        for (int off = 16; off > 0; off >>= 1)
            v += __shfl_xor_sync(0xFFFFFFFFu, v, off);
        if (lane == 0) {
            out[0] = (float)(v / (double)B_TOTAL);
            g_counter = 0;                        // reset for next graph replay
        }
    }
}

extern "C" void kernel_launch(void* const* d_in, const int* in_sizes, int n_in,
                              void* d_out, int out_size) {
    const float4* logits2 = (const float4*)d_in[0];
    const int2*   labels2 = (const int2*)d_in[1];
    float* out = (float*)d_out;

    loss_fused<<<GRID1, BLK1>>>(logits2, labels2, out);
}